// round 10
// baseline (speedup 1.0000x reference)
#include <cuda_runtime.h>
#include <cuda_bf16.h>
#include <cstdint>

#define N_NODES  200000
#define N_EDGES  800000
#define IN_CH    128
#define OUT_CH   64
#define MAX_DEG  4
#define N_GRAPHS 8192

// ---------------- scratch ----------------
__device__ int    fpnn_stride;                        // 1 = int32 inputs, 2 = int64
__device__ int    fpnn_deg[N_NODES];
__device__ int    fpnn_off[N_NODES];
__device__ int    fpnn_fill[N_NODES];
__device__ int    fpnn_csr[N_EDGES];
__device__ int    fpnn_cnt[8];                        // [0..4] buckets, [5] cursor
__device__ int    fpnn_lists[(MAX_DEG + 1) * N_NODES];
__device__ uint2  fpnn_wsp[40960];                    // pre-split weights: (d*4+chunk)*2048 + ch*32 + kh
__device__ float2 fpnn_pre2[(size_t)N_NODES * (OUT_CH / 2)];  // 51.2 MB

// ---------------- degree count (+ block-local dtype detect) ----------------
__global__ void fpnn_deg_kernel(const int* __restrict__ ei32) {
    __shared__ int s_st;
    if (threadIdx.x == 0) {
        int nz = 0;
#pragma unroll
        for (int j = 0; j < 8; j++) nz |= ei32[2 * j + 1];
        int st = (nz == 0) ? 2 : 1;
        s_st = st;
        if (blockIdx.x == 0) fpnn_stride = st;
    }
    __syncthreads();
    int e = blockIdx.x * blockDim.x + threadIdx.x;
    if (e >= N_EDGES) return;
    int dst = ei32[(size_t)s_st * (N_EDGES + e)];
    atomicAdd(&fpnn_deg[dst], 1);
}

// ---------------- split-bf16 helpers ----------------
__device__ __forceinline__ unsigned fpnn_pack(float f0, float f1) {
    unsigned u0 = (unsigned)__bfloat16_as_ushort(__float2bfloat16_rn(f0));
    unsigned u1 = (unsigned)__bfloat16_as_ushort(__float2bfloat16_rn(f1));
    return (u1 << 16) | u0;   // element k in low half
}
__device__ __forceinline__ uint2 fpnn_split2(float f0, float f1) {
    float h0 = __bfloat162float(__float2bfloat16_rn(f0));
    float h1 = __bfloat162float(__float2bfloat16_rn(f1));
    uint2 p;
    p.x = fpnn_pack(h0, h1);
    p.y = fpnn_pack(f0 - h0, f1 - h1);
    return p;
}
// bank-rotated smem index (uint2 elements, 32 per row); coeff 5 invertible mod 16
__device__ __forceinline__ int fpnn_sw5(int row, int khalf) {
    return row * 32 + ((khalf + row * 5) & 31);
}

// ---------------- offset alloc + bucketize + weight pre-split ----------------
__global__ void fpnn_alloc_kernel(const float* __restrict__ Wlin,
                                  const float* __restrict__ Wroot) {
    int n = blockIdx.x * blockDim.x + threadIdx.x;
    if (n < N_NODES) {
        int deg = fpnn_deg[n];
        fpnn_off[n] = atomicAdd(&fpnn_cnt[5], deg);
        fpnn_fill[n] = 0;
        int d = min(deg, MAX_DEG);
        int pos = atomicAdd(&fpnn_cnt[d], 1);
        fpnn_lists[d * N_NODES + pos] = n;
    }
    if (n < 40960) {
        int kh = n & 31;
        int ch = (n >> 5) & 63;
        int dc = n >> 11;               // d*4 + chunk
        int d = dc >> 2, chunk = dc & 3;
        const float* w = (chunk < 2)
            ? Wlin  + (size_t)d * IN_CH * OUT_CH + (size_t)(chunk * 64) * OUT_CH
            : Wroot + (size_t)d * IN_CH * OUT_CH + (size_t)((chunk - 2) * 64) * OUT_CH;
        int k0 = kh * 2;
        float f0 = w[(size_t)k0 * OUT_CH + ch];
        float f1 = w[(size_t)(k0 + 1) * OUT_CH + ch];
        fpnn_wsp[n] = fpnn_split2(f0, f1);
    }
}

// ---------------- fill CSR ----------------
__global__ void fpnn_fill_kernel(const int* __restrict__ ei32) {
    int e = blockIdx.x * blockDim.x + threadIdx.x;
    if (e >= N_EDGES) return;
    int st = fpnn_stride;
    int src = ei32[(size_t)st * e];
    int dst = ei32[(size_t)st * (N_EDGES + e)];
    int pos = fpnn_off[dst] + atomicAdd(&fpnn_fill[dst], 1);
    fpnn_csr[pos] = src;
}

#define FPNN_MMA(d, a0, a1, a2, a3, b0, b1)                                   \
    asm volatile(                                                             \
        "mma.sync.aligned.m16n8k16.row.col.f32.bf16.bf16.f32 "                \
        "{%0,%1,%2,%3},{%4,%5,%6,%7},{%8,%9},{%0,%1,%2,%3};"                  \
        : "+f"(d[0]), "+f"(d[1]), "+f"(d[2]), "+f"(d[3])                      \
        : "r"(a0), "r"(a1), "r"(a2), "r"(a3), "r"(b0), "r"(b1))

// ---------------- fused gather + split-bf16 tensor GEMM ----------------
// pre[n] = (sum_{src} x[src]) @ Wlin[d] + x[n] @ Wroot[d]
// A[count x 256] (agg||x) @ B[256 x 64] ([Wlin;Wroot]); 3-term hi/lo split.
// Tile 64 nodes x 64 ch; K in 4 chunks of 64. Block 256 thr = 8 warps (4 M x 2 N).
#define GX2 148
#define M_TILE 64
__global__ void __launch_bounds__(256)
fpnn_mma_kernel(const float4* __restrict__ x4) {
    __shared__ uint2 A_s[64 * 32];   // [node][khalf] {hi-pair, lo-pair}, 16 KB
    __shared__ uint2 B_s[64 * 32];   // [ch][khalf], 16 KB

    int d = blockIdx.y;
    int count = fpnn_cnt[d];
    const int* list = fpnn_lists + d * N_NODES;

    int tid = threadIdx.x;
    int nl = tid >> 2, kt = tid & 3;          // A loader: node slot x k-sixteenth
    int bn = tid & 63, bkg = tid >> 6;        // B loader: channel x k-quarter(16)
    int wid = tid >> 5, lane = tid & 31;
    int m0 = (wid & 3) * 16, n0 = (wid >> 2) * 32;
    int g = lane >> 2, t = lane & 3;

    for (int tile = blockIdx.x; tile * M_TILE < count; tile += GX2) {
        float acc[4][4];
#pragma unroll
        for (int i = 0; i < 4; i++)
#pragma unroll
            for (int j = 0; j < 4; j++) acc[i][j] = 0.f;

#pragma unroll
        for (int chunk = 0; chunk < 4; chunk++) {
            // ---- A chunk: gathered agg (chunks 0,1) or own x (chunks 2,3) ----
            float v[16];
#pragma unroll
            for (int j = 0; j < 16; j++) v[j] = 0.f;
            int nidx = tile * M_TILE + nl;
            if (nidx < count) {
                int n = list[nidx];
                if (chunk < 2) {
                    int deg = fpnn_deg[n];
                    int off = fpnn_off[n];
                    int cb = chunk * 16 + kt * 4;
                    int i = 0;
                    for (; i + 2 <= deg; i += 2) {       // unroll-2 for MLP
                        int s0 = fpnn_csr[off + i];
                        int s1 = fpnn_csr[off + i + 1];
                        const float4* r0 = x4 + (size_t)s0 * 32 + cb;
                        const float4* r1 = x4 + (size_t)s1 * 32 + cb;
#pragma unroll
                        for (int q = 0; q < 4; q++) {
                            float4 a = r0[q], b = r1[q];
                            v[4*q+0] += a.x + b.x; v[4*q+1] += a.y + b.y;
                            v[4*q+2] += a.z + b.z; v[4*q+3] += a.w + b.w;
                        }
                    }
                    if (i < deg) {
                        int s0 = fpnn_csr[off + i];
                        const float4* r0 = x4 + (size_t)s0 * 32 + cb;
#pragma unroll
                        for (int q = 0; q < 4; q++) {
                            float4 a = r0[q];
                            v[4*q+0] += a.x; v[4*q+1] += a.y;
                            v[4*q+2] += a.z; v[4*q+3] += a.w;
                        }
                    }
                } else {
                    const float4* r = x4 + (size_t)n * 32 + (chunk - 2) * 16 + kt * 4;
#pragma unroll
                    for (int q = 0; q < 4; q++) {
                        float4 a = r[q];
                        v[4*q+0] = a.x; v[4*q+1] = a.y;
                        v[4*q+2] = a.z; v[4*q+3] = a.w;
                    }
                }
            }
#pragma unroll
            for (int jj = 0; jj < 8; jj++)
                A_s[fpnn_sw5(nl, kt * 8 + jj)] = fpnn_split2(v[2*jj], v[2*jj+1]);

            // ---- B chunk: direct copy of pre-split weights ----
            {
                const uint2* wsrc = fpnn_wsp + ((d * 4 + chunk) * 64 + bn) * 32 + bkg * 8;
#pragma unroll
                for (int jj = 0; jj < 8; jj++)
                    B_s[fpnn_sw5(bn, bkg * 8 + jj)] = wsrc[jj];
            }
            __syncthreads();

            // ---- mma: 4 k-steps of 16 ----
#pragma unroll
            for (int ks = 0; ks < 4; ks++) {
                int kh = ks * 8 + t;
                uint2 A0 = A_s[fpnn_sw5(m0 + g,     kh)];
                uint2 A1 = A_s[fpnn_sw5(m0 + g + 8, kh)];
                uint2 A2 = A_s[fpnn_sw5(m0 + g,     kh + 4)];
                uint2 A3 = A_s[fpnn_sw5(m0 + g + 8, kh + 4)];
#pragma unroll
                for (int ns = 0; ns < 4; ns++) {
                    int n = n0 + ns * 8 + g;
                    uint2 B0 = B_s[fpnn_sw5(n, kh)];
                    uint2 B1 = B_s[fpnn_sw5(n, kh + 4)];
                    FPNN_MMA(acc[ns], A0.x, A1.x, A2.x, A3.x, B0.x, B1.x); // hi*hi
                    FPNN_MMA(acc[ns], A0.x, A1.x, A2.x, A3.x, B0.y, B1.y); // hi*lo
                    FPNN_MMA(acc[ns], A0.y, A1.y, A2.y, A3.y, B0.x, B1.x); // lo*hi
                }
            }
            __syncthreads();
        }

        // ---- store ----
        int r0 = tile * M_TILE + m0 + g;
        int r1 = r0 + 8;
#pragma unroll
        for (int ns = 0; ns < 4; ns++) {
            int ncol_half = (n0 >> 1) + ns * 4 + t;
            if (r0 < count) {
                int n = list[r0];
                fpnn_pre2[(size_t)n * 32 + ncol_half] = make_float2(acc[ns][0], acc[ns][1]);
            }
            if (r1 < count) {
                int n = list[r1];
                fpnn_pre2[(size_t)n * 32 + ncol_half] = make_float2(acc[ns][2], acc[ns][3]);
            }
        }
    }
}

// ---------------- fused relu + softmax + pool (warp per 8 sorted nodes) ---------
#define NODES_PER_WARP 8
__global__ void fpnn_spool_kernel(const int* __restrict__ b32,
                                  float* __restrict__ out) {
    int warp = (blockIdx.x * blockDim.x + threadIdx.x) >> 5;
    int lane = threadIdx.x & 31;
    int n0 = warp * NODES_PER_WARP;
    if (n0 >= N_NODES) return;
    int st = fpnn_stride;

    float2 acc = make_float2(0.f, 0.f);
    int gcur = b32[(size_t)st * n0];

#pragma unroll
    for (int i = 0; i < NODES_PER_WARP; i++) {
        int n = n0 + i;
        int g = b32[(size_t)st * n];
        if (g != gcur) {
            atomicAdd(out + (size_t)gcur * OUT_CH + 2 * lane,     acc.x);
            atomicAdd(out + (size_t)gcur * OUT_CH + 2 * lane + 1, acc.y);
            acc = make_float2(0.f, 0.f);
            gcur = g;
        }
        float2 v = fpnn_pre2[(size_t)n * 32 + lane];
        v.x = fmaxf(v.x, 0.f);
        v.y = fmaxf(v.y, 0.f);
        float m = fmaxf(v.x, v.y);
#pragma unroll
        for (int s = 16; s; s >>= 1) m = fmaxf(m, __shfl_xor_sync(0xffffffffu, m, s));
        float ex = __expf(v.x - m), ey = __expf(v.y - m);
        float s = ex + ey;
#pragma unroll
        for (int ss = 16; ss; ss >>= 1) s += __shfl_xor_sync(0xffffffffu, s, ss);
        float inv = 1.0f / s;
        acc.x += ex * inv;
        acc.y += ey * inv;
    }
    atomicAdd(out + (size_t)gcur * OUT_CH + 2 * lane,     acc.x);
    atomicAdd(out + (size_t)gcur * OUT_CH + 2 * lane + 1, acc.y);
}

// ---------------- launch ----------------
extern "C" void kernel_launch(void* const* d_in, const int* in_sizes, int n_in,
                              void* d_out, int out_size) {
    const float* x = 0; const int* ei32 = 0; const int* b32 = 0;
    const float* Wlin = 0; const float* Wroot = 0;
    for (int i = 0; i < n_in; i++) {
        int s = in_sizes[i];
        if      (s == N_NODES * IN_CH)        x    = (const float*)d_in[i];
        else if (s == 2 * N_EDGES)            ei32 = (const int*)d_in[i];
        else if (s == N_NODES)                b32  = (const int*)d_in[i];
        else if (s == (MAX_DEG + 1) * IN_CH * OUT_CH) {
            if (!Wlin) Wlin = (const float*)d_in[i];
            else       Wroot = (const float*)d_in[i];
        }
    }
    if (!x)     x     = (const float*)d_in[0];
    if (!ei32)  ei32  = (const int*)d_in[1];
    if (!b32)   b32   = (const int*)d_in[2];
    if (!Wlin)  Wlin  = (const float*)d_in[3];
    if (!Wroot) Wroot = (const float*)d_in[4];
    float* out = (float*)d_out;

    // zeroing via capturable memset nodes (no kernel slot used)
    void* p_deg = 0; void* p_cnt = 0;
    cudaGetSymbolAddress(&p_deg, fpnn_deg);
    cudaGetSymbolAddress(&p_cnt, fpnn_cnt);
    cudaMemsetAsync(p_deg, 0, N_NODES * sizeof(int));
    cudaMemsetAsync(p_cnt, 0, 8 * sizeof(int));
    cudaMemsetAsync(d_out, 0, (size_t)out_size * sizeof(float));

    fpnn_deg_kernel<<<(N_EDGES + 255) / 256, 256>>>(ei32);
    fpnn_alloc_kernel<<<(N_NODES + 255) / 256, 256>>>(Wlin, Wroot);
    fpnn_fill_kernel<<<(N_EDGES + 255) / 256, 256>>>(ei32);
    fpnn_mma_kernel<<<dim3(GX2, MAX_DEG + 1), 256>>>((const float4*)x);
    fpnn_spool_kernel<<<(N_NODES / NODES_PER_WARP * 32 + 255) / 256, 256>>>(b32, out);
}

// round 11
// speedup vs baseline: 1.3789x; 1.3789x over previous
#include <cuda_runtime.h>
#include <cuda_bf16.h>
#include <cstdint>

#define N_NODES  200000
#define N_EDGES  800000
#define IN_CH    128
#define OUT_CH   64
#define MAX_DEG  4
#define N_GRAPHS 8192

// ---------------- scratch ----------------
__device__ int    fpnn_stride;                        // 1 = int32 inputs, 2 = int64
__device__ int    fpnn_deg[N_NODES];
__device__ int    fpnn_off[N_NODES];
__device__ int    fpnn_fill[N_NODES];
__device__ int    fpnn_csr[N_EDGES];
__device__ int    fpnn_cnt[8];                        // [0..4] buckets, [5] cursor
__device__ int    fpnn_lists[(MAX_DEG + 1) * N_NODES];
__device__ uint2  fpnn_wsp[40960];                    // pre-split weights
__device__ float2 fpnn_pre2[(size_t)N_NODES * (OUT_CH / 2)];  // 51.2 MB

// ---------------- degree count (+ block-local dtype detect) ----------------
__global__ void fpnn_deg_kernel(const int* __restrict__ ei32) {
    __shared__ int s_st;
    if (threadIdx.x == 0) {
        int nz = 0;
#pragma unroll
        for (int j = 0; j < 8; j++) nz |= ei32[2 * j + 1];
        int st = (nz == 0) ? 2 : 1;
        s_st = st;
        if (blockIdx.x == 0) fpnn_stride = st;
    }
    __syncthreads();
    int e = blockIdx.x * blockDim.x + threadIdx.x;
    if (e >= N_EDGES) return;
    int dst = ei32[(size_t)s_st * (N_EDGES + e)];
    atomicAdd(&fpnn_deg[dst], 1);
}

// ---------------- split-bf16 helpers ----------------
__device__ __forceinline__ unsigned fpnn_pack(float f0, float f1) {
    unsigned u0 = (unsigned)__bfloat16_as_ushort(__float2bfloat16_rn(f0));
    unsigned u1 = (unsigned)__bfloat16_as_ushort(__float2bfloat16_rn(f1));
    return (u1 << 16) | u0;
}
__device__ __forceinline__ uint2 fpnn_split2(float f0, float f1) {
    float h0 = __bfloat162float(__float2bfloat16_rn(f0));
    float h1 = __bfloat162float(__float2bfloat16_rn(f1));
    uint2 p;
    p.x = fpnn_pack(h0, h1);
    p.y = fpnn_pack(f0 - h0, f1 - h1);
    return p;
}
// bank-rotated smem index (uint2 elements, 32 per row); coeff 5 invertible mod 16
__device__ __forceinline__ int fpnn_sw5(int row, int khalf) {
    return row * 32 + ((khalf + row * 5) & 31);
}

// ---------------- offset alloc + bucketize + weight pre-split ----------------
__global__ void fpnn_alloc_kernel(const float* __restrict__ Wlin,
                                  const float* __restrict__ Wroot) {
    int n = blockIdx.x * blockDim.x + threadIdx.x;
    if (n < N_NODES) {
        int deg = fpnn_deg[n];
        fpnn_off[n] = atomicAdd(&fpnn_cnt[5], deg);
        fpnn_fill[n] = 0;
        int d = min(deg, MAX_DEG);
        int pos = atomicAdd(&fpnn_cnt[d], 1);
        fpnn_lists[d * N_NODES + pos] = n;
    }
    if (n < 40960) {
        int kh = n & 31;
        int ch = (n >> 5) & 63;
        int dc = n >> 11;               // d*4 + chunk
        int d = dc >> 2, chunk = dc & 3;
        const float* w = (chunk < 2)
            ? Wlin  + (size_t)d * IN_CH * OUT_CH + (size_t)(chunk * 64) * OUT_CH
            : Wroot + (size_t)d * IN_CH * OUT_CH + (size_t)((chunk - 2) * 64) * OUT_CH;
        int k0 = kh * 2;
        float f0 = w[(size_t)k0 * OUT_CH + ch];
        float f1 = w[(size_t)(k0 + 1) * OUT_CH + ch];
        fpnn_wsp[n] = fpnn_split2(f0, f1);
    }
}

// ---------------- fill CSR ----------------
__global__ void fpnn_fill_kernel(const int* __restrict__ ei32) {
    int e = blockIdx.x * blockDim.x + threadIdx.x;
    if (e >= N_EDGES) return;
    int st = fpnn_stride;
    int src = ei32[(size_t)st * e];
    int dst = ei32[(size_t)st * (N_EDGES + e)];
    int pos = fpnn_off[dst] + atomicAdd(&fpnn_fill[dst], 1);
    fpnn_csr[pos] = src;
}

#define FPNN_MMA(d, a0, a1, a2, a3, b0, b1)                                   \
    asm volatile(                                                             \
        "mma.sync.aligned.m16n8k16.row.col.f32.bf16.bf16.f32 "                \
        "{%0,%1,%2,%3},{%4,%5,%6,%7},{%8,%9},{%0,%1,%2,%3};"                  \
        : "+f"(d[0]), "+f"(d[1]), "+f"(d[2]), "+f"(d[3])                      \
        : "r"(a0), "r"(a1), "r"(a2), "r"(a3), "r"(b0), "r"(b1))

// ---------------- fused gather + split-bf16 tensor GEMM ----------------
// One block per tile; (bucket, tile) derived from prefix of bucket tile counts.
#define M_TILE 64
#define MAX_TILES ((N_NODES + M_TILE - 1) / M_TILE + MAX_DEG + 1)   // 3130
__global__ void __launch_bounds__(256, 3)
fpnn_mma_kernel(const float4* __restrict__ x4) {
    __shared__ uint2 A_s[64 * 32];   // [node][khalf] {hi-pair, lo-pair}, 16 KB
    __shared__ uint2 B_s[64 * 32];   // [ch][khalf], 16 KB

    // flattened tile -> (bucket d, tile) via prefix over per-bucket tile counts
    int tg = blockIdx.x;
    int d = 0, tile = 0, count = 0;
    {
        int base = 0;
        bool found = false;
#pragma unroll
        for (int b = 0; b <= MAX_DEG; b++) {
            int c = fpnn_cnt[b];
            int t = (c + M_TILE - 1) >> 6;
            if (!found && tg < base + t) {
                d = b; tile = tg - base; count = c; found = true;
            }
            base += t;
        }
        if (!found) return;
    }

    const int* list = fpnn_lists + d * N_NODES;

    int tid = threadIdx.x;
    int nl = tid >> 2, kt = tid & 3;          // A loader: node slot x k-sixteenth
    int bn = tid & 63, bkg = tid >> 6;        // B loader: channel x k-quarter
    int wid = tid >> 5, lane = tid & 31;
    int m0 = (wid & 3) * 16, n0 = (wid >> 2) * 32;
    int g = lane >> 2, t = lane & 3;

    float acc[4][4];
#pragma unroll
    for (int i = 0; i < 4; i++)
#pragma unroll
        for (int j = 0; j < 4; j++) acc[i][j] = 0.f;

#pragma unroll
    for (int chunk = 0; chunk < 4; chunk++) {
        // ---- A chunk: gathered agg (chunks 0,1) or own x (chunks 2,3) ----
        float v[16];
#pragma unroll
        for (int j = 0; j < 16; j++) v[j] = 0.f;
        int nidx = tile * M_TILE + nl;
        if (nidx < count) {
            int n = list[nidx];
            if (chunk < 2) {
                int deg = fpnn_deg[n];
                int off = fpnn_off[n];
                int cb = chunk * 16 + kt * 4;
                for (int i = 0; i < deg; i++) {
                    int src = fpnn_csr[off + i];
                    const float4* r = x4 + (size_t)src * 32 + cb;
#pragma unroll
                    for (int q = 0; q < 4; q++) {
                        float4 a = r[q];
                        v[4*q+0] += a.x; v[4*q+1] += a.y;
                        v[4*q+2] += a.z; v[4*q+3] += a.w;
                    }
                }
            } else {
                const float4* r = x4 + (size_t)n * 32 + (chunk - 2) * 16 + kt * 4;
#pragma unroll
                for (int q = 0; q < 4; q++) {
                    float4 a = r[q];
                    v[4*q+0] = a.x; v[4*q+1] = a.y;
                    v[4*q+2] = a.z; v[4*q+3] = a.w;
                }
            }
        }
#pragma unroll
        for (int jj = 0; jj < 8; jj++)
            A_s[fpnn_sw5(nl, kt * 8 + jj)] = fpnn_split2(v[2*jj], v[2*jj+1]);

        // ---- B chunk: direct copy of pre-split weights ----
        {
            const uint2* wsrc = fpnn_wsp + ((d * 4 + chunk) * 64 + bn) * 32 + bkg * 8;
#pragma unroll
            for (int jj = 0; jj < 8; jj++)
                B_s[fpnn_sw5(bn, bkg * 8 + jj)] = wsrc[jj];
        }
        __syncthreads();

        // ---- mma: 4 k-steps of 16 ----
#pragma unroll
        for (int ks = 0; ks < 4; ks++) {
            int kh = ks * 8 + t;
            uint2 A0 = A_s[fpnn_sw5(m0 + g,     kh)];
            uint2 A1 = A_s[fpnn_sw5(m0 + g + 8, kh)];
            uint2 A2 = A_s[fpnn_sw5(m0 + g,     kh + 4)];
            uint2 A3 = A_s[fpnn_sw5(m0 + g + 8, kh + 4)];
#pragma unroll
            for (int ns = 0; ns < 4; ns++) {
                int n = n0 + ns * 8 + g;
                uint2 B0 = B_s[fpnn_sw5(n, kh)];
                uint2 B1 = B_s[fpnn_sw5(n, kh + 4)];
                FPNN_MMA(acc[ns], A0.x, A1.x, A2.x, A3.x, B0.x, B1.x); // hi*hi
                FPNN_MMA(acc[ns], A0.x, A1.x, A2.x, A3.x, B0.y, B1.y); // hi*lo
                FPNN_MMA(acc[ns], A0.y, A1.y, A2.y, A3.y, B0.x, B1.x); // lo*hi
            }
        }
        __syncthreads();
    }

    // ---- store ----
    int r0 = tile * M_TILE + m0 + g;
    int r1 = r0 + 8;
#pragma unroll
    for (int ns = 0; ns < 4; ns++) {
        int ncol_half = (n0 >> 1) + ns * 4 + t;
        if (r0 < count) {
            int n = list[r0];
            fpnn_pre2[(size_t)n * 32 + ncol_half] = make_float2(acc[ns][0], acc[ns][1]);
        }
        if (r1 < count) {
            int n = list[r1];
            fpnn_pre2[(size_t)n * 32 + ncol_half] = make_float2(acc[ns][2], acc[ns][3]);
        }
    }
}

// ---------------- fused relu + softmax + pool (warp per 8 sorted nodes) ---------
#define NODES_PER_WARP 8
__global__ void fpnn_spool_kernel(const int* __restrict__ b32,
                                  float* __restrict__ out) {
    int warp = (blockIdx.x * blockDim.x + threadIdx.x) >> 5;
    int lane = threadIdx.x & 31;
    int n0 = warp * NODES_PER_WARP;
    if (n0 >= N_NODES) return;
    int st = fpnn_stride;

    float2 acc = make_float2(0.f, 0.f);
    int gcur = b32[(size_t)st * n0];

#pragma unroll
    for (int i = 0; i < NODES_PER_WARP; i++) {
        int n = n0 + i;
        int g = b32[(size_t)st * n];
        if (g != gcur) {
            atomicAdd(out + (size_t)gcur * OUT_CH + 2 * lane,     acc.x);
            atomicAdd(out + (size_t)gcur * OUT_CH + 2 * lane + 1, acc.y);
            acc = make_float2(0.f, 0.f);
            gcur = g;
        }
        float2 v = fpnn_pre2[(size_t)n * 32 + lane];
        v.x = fmaxf(v.x, 0.f);
        v.y = fmaxf(v.y, 0.f);
        float m = fmaxf(v.x, v.y);
#pragma unroll
        for (int s = 16; s; s >>= 1) m = fmaxf(m, __shfl_xor_sync(0xffffffffu, m, s));
        float ex = __expf(v.x - m), ey = __expf(v.y - m);
        float s = ex + ey;
#pragma unroll
        for (int ss = 16; ss; ss >>= 1) s += __shfl_xor_sync(0xffffffffu, s, ss);
        float inv = 1.0f / s;
        acc.x += ex * inv;
        acc.y += ey * inv;
    }
    atomicAdd(out + (size_t)gcur * OUT_CH + 2 * lane,     acc.x);
    atomicAdd(out + (size_t)gcur * OUT_CH + 2 * lane + 1, acc.y);
}

// ---------------- launch ----------------
extern "C" void kernel_launch(void* const* d_in, const int* in_sizes, int n_in,
                              void* d_out, int out_size) {
    const float* x = 0; const int* ei32 = 0; const int* b32 = 0;
    const float* Wlin = 0; const float* Wroot = 0;
    for (int i = 0; i < n_in; i++) {
        int s = in_sizes[i];
        if      (s == N_NODES * IN_CH)        x    = (const float*)d_in[i];
        else if (s == 2 * N_EDGES)            ei32 = (const int*)d_in[i];
        else if (s == N_NODES)                b32  = (const int*)d_in[i];
        else if (s == (MAX_DEG + 1) * IN_CH * OUT_CH) {
            if (!Wlin) Wlin = (const float*)d_in[i];
            else       Wroot = (const float*)d_in[i];
        }
    }
    if (!x)     x     = (const float*)d_in[0];
    if (!ei32)  ei32  = (const int*)d_in[1];
    if (!b32)   b32   = (const int*)d_in[2];
    if (!Wlin)  Wlin  = (const float*)d_in[3];
    if (!Wroot) Wroot = (const float*)d_in[4];
    float* out = (float*)d_out;

    void* p_deg = 0; void* p_cnt = 0;
    cudaGetSymbolAddress(&p_deg, fpnn_deg);
    cudaGetSymbolAddress(&p_cnt, fpnn_cnt);
    cudaMemsetAsync(p_deg, 0, N_NODES * sizeof(int));
    cudaMemsetAsync(p_cnt, 0, 8 * sizeof(int));
    cudaMemsetAsync(d_out, 0, (size_t)out_size * sizeof(float));

    fpnn_deg_kernel<<<(N_EDGES + 255) / 256, 256>>>(ei32);
    fpnn_alloc_kernel<<<(N_NODES + 255) / 256, 256>>>(Wlin, Wroot);
    fpnn_fill_kernel<<<(N_EDGES + 255) / 256, 256>>>(ei32);
    fpnn_mma_kernel<<<MAX_TILES, 256>>>((const float4*)x);
    fpnn_spool_kernel<<<(N_NODES / NODES_PER_WARP * 32 + 255) / 256, 256>>>(b32, out);
}

// round 12
// speedup vs baseline: 1.5376x; 1.1151x over previous
#include <cuda_runtime.h>
#include <cuda_bf16.h>
#include <cstdint>

#define N_NODES  200000
#define N_EDGES  800000
#define IN_CH    128
#define OUT_CH   64
#define MAX_DEG  4
#define N_GRAPHS 8192

// ---------------- scratch ----------------
__device__ int    fpnn_stride;                        // 1 = int32 inputs, 2 = int64
__device__ int    fpnn_deg[N_NODES];
__device__ int    fpnn_off[N_NODES];
__device__ int    fpnn_fill[N_NODES];
__device__ int    fpnn_csr[N_EDGES];
__device__ int    fpnn_cnt[8];                        // [0..4] buckets, [5] cursor
__device__ int    fpnn_lists[(MAX_DEG + 1) * N_NODES];
__device__ uint4  fpnn_wsp4[20480];                   // fragment-ordered split weights
__device__ float2 fpnn_pre2[(size_t)N_NODES * (OUT_CH / 2)];  // 51.2 MB

// ---------------- degree count (+ block-local dtype detect) ----------------
__global__ void fpnn_deg_kernel(const int* __restrict__ ei32) {
    __shared__ int s_st;
    if (threadIdx.x == 0) {
        int nz = 0;
#pragma unroll
        for (int j = 0; j < 8; j++) nz |= ei32[2 * j + 1];
        int st = (nz == 0) ? 2 : 1;
        s_st = st;
        if (blockIdx.x == 0) fpnn_stride = st;
    }
    __syncthreads();
    int e = blockIdx.x * blockDim.x + threadIdx.x;
    if (e >= N_EDGES) return;
    int dst = ei32[(size_t)s_st * (N_EDGES + e)];
    atomicAdd(&fpnn_deg[dst], 1);
}

// ---------------- split-bf16 helpers ----------------
__device__ __forceinline__ unsigned fpnn_pack(float f0, float f1) {
    unsigned u0 = (unsigned)__bfloat16_as_ushort(__float2bfloat16_rn(f0));
    unsigned u1 = (unsigned)__bfloat16_as_ushort(__float2bfloat16_rn(f1));
    return (u1 << 16) | u0;
}
__device__ __forceinline__ uint2 fpnn_split2(float f0, float f1) {
    float h0 = __bfloat162float(__float2bfloat16_rn(f0));
    float h1 = __bfloat162float(__float2bfloat16_rn(f1));
    uint2 p;
    p.x = fpnn_pack(h0, h1);
    p.y = fpnn_pack(f0 - h0, f1 - h1);
    return p;
}
// uint4-cell smem index with XOR bank swizzle; 16 cells per row
__device__ __forceinline__ int fpnn_swx(int row, int c) {
    return row * 16 + (c ^ (row & 7));
}

// ---------------- offset alloc + bucketize + weight pre-split (fragment order) --
// wsp4[((d*4+chunk)*64 + ch)*16 + cell], cell = a*4+u covers khalves a*8+u, a*8+u+4
__global__ void fpnn_alloc_kernel(const float* __restrict__ Wlin,
                                  const float* __restrict__ Wroot) {
    int n = blockIdx.x * blockDim.x + threadIdx.x;
    if (n < N_NODES) {
        int deg = fpnn_deg[n];
        fpnn_off[n] = atomicAdd(&fpnn_cnt[5], deg);
        fpnn_fill[n] = 0;
        int d = min(deg, MAX_DEG);
        int pos = atomicAdd(&fpnn_cnt[d], 1);
        fpnn_lists[d * N_NODES + pos] = n;
    }
    if (n < 20480) {
        int cell = n & 15;
        int ch = (n >> 4) & 63;
        int dc = n >> 10;               // d*4 + chunk, 0..19
        int d = dc >> 2, chunk = dc & 3;
        const float* w = (chunk < 2)
            ? Wlin  + (size_t)d * IN_CH * OUT_CH + (size_t)(chunk * 64) * OUT_CH
            : Wroot + (size_t)d * IN_CH * OUT_CH + (size_t)((chunk - 2) * 64) * OUT_CH;
        int a = cell >> 2, u = cell & 3;
        int k0 = (a * 8 + u) * 2;       // khalf kh1 = a*8+u -> k = 2*kh1
        float f0 = w[(size_t)k0 * OUT_CH + ch];
        float f1 = w[(size_t)(k0 + 1) * OUT_CH + ch];
        float f2 = w[(size_t)(k0 + 8) * OUT_CH + ch];   // kh2 = kh1+4 -> k+8
        float f3 = w[(size_t)(k0 + 9) * OUT_CH + ch];
        uint2 p1 = fpnn_split2(f0, f1);
        uint2 p2 = fpnn_split2(f2, f3);
        uint4 q; q.x = p1.x; q.y = p1.y; q.z = p2.x; q.w = p2.y;
        fpnn_wsp4[n] = q;
    }
}

// ---------------- fill CSR ----------------
__global__ void fpnn_fill_kernel(const int* __restrict__ ei32) {
    int e = blockIdx.x * blockDim.x + threadIdx.x;
    if (e >= N_EDGES) return;
    int st = fpnn_stride;
    int src = ei32[(size_t)st * e];
    int dst = ei32[(size_t)st * (N_EDGES + e)];
    int pos = fpnn_off[dst] + atomicAdd(&fpnn_fill[dst], 1);
    fpnn_csr[pos] = src;
}

#define FPNN_MMA(d, a0, a1, a2, a3, b0, b1)                                   \
    asm volatile(                                                             \
        "mma.sync.aligned.m16n8k16.row.col.f32.bf16.bf16.f32 "                \
        "{%0,%1,%2,%3},{%4,%5,%6,%7},{%8,%9},{%0,%1,%2,%3};"                  \
        : "+f"(d[0]), "+f"(d[1]), "+f"(d[2]), "+f"(d[3])                      \
        : "r"(a0), "r"(a1), "r"(a2), "r"(a3), "r"(b0), "r"(b1))

// ---------------- fused gather + split-bf16 tensor GEMM ----------------
// One block per tile; (bucket d, tile) from prefix over bucket tile counts.
// uint4 cell = {hi(kh), lo(kh), hi(kh+4), lo(kh+4)} -> one LDS.128 per fragment pair.
#define M_TILE 64
#define MAX_TILES ((N_NODES + M_TILE - 1) / M_TILE + MAX_DEG + 1)   // 3130
__global__ void __launch_bounds__(256, 3)
fpnn_mma_kernel(const float4* __restrict__ x4) {
    __shared__ uint4 A_s[64 * 16];   // [node][cell], 16 KB
    __shared__ uint4 B_s[64 * 16];   // [ch][cell], 16 KB

    int tg = blockIdx.x;
    int d = 0, tile = 0, count = 0;
    {
        int base = 0;
        bool found = false;
#pragma unroll
        for (int b = 0; b <= MAX_DEG; b++) {
            int c = fpnn_cnt[b];
            int t = (c + M_TILE - 1) >> 6;
            if (!found && tg < base + t) {
                d = b; tile = tg - base; count = c; found = true;
            }
            base += t;
        }
        if (!found) return;
    }

    const int* list = fpnn_lists + d * N_NODES;

    int tid = threadIdx.x;
    int nl = tid >> 2, kt = tid & 3;          // A loader: node slot x k-sixteenth
    int bn = tid & 63, bkg = tid >> 6;        // B loader: channel x cell-quarter
    int wid = tid >> 5, lane = tid & 31;
    int m0 = (wid & 3) * 16, n0 = (wid >> 2) * 32;
    int g = lane >> 2, t = lane & 3;

    float acc[4][4];
#pragma unroll
    for (int i = 0; i < 4; i++)
#pragma unroll
        for (int j = 0; j < 4; j++) acc[i][j] = 0.f;

#pragma unroll
    for (int chunk = 0; chunk < 4; chunk++) {
        // ---- A chunk: gathered agg (chunks 0,1) or own x (chunks 2,3) ----
        float v[16];
#pragma unroll
        for (int j = 0; j < 16; j++) v[j] = 0.f;
        int nidx = tile * M_TILE + nl;
        if (nidx < count) {
            int n = list[nidx];
            if (chunk < 2) {
                int deg = fpnn_deg[n];
                int off = fpnn_off[n];
                int cb = chunk * 16 + kt * 4;
                for (int i = 0; i < deg; i++) {
                    int src = fpnn_csr[off + i];
                    const float4* r = x4 + (size_t)src * 32 + cb;
#pragma unroll
                    for (int q = 0; q < 4; q++) {
                        float4 a = r[q];
                        v[4*q+0] += a.x; v[4*q+1] += a.y;
                        v[4*q+2] += a.z; v[4*q+3] += a.w;
                    }
                }
            } else {
                const float4* r = x4 + (size_t)n * 32 + (chunk - 2) * 16 + kt * 4;
#pragma unroll
                for (int q = 0; q < 4; q++) {
                    float4 a = r[q];
                    v[4*q+0] = a.x; v[4*q+1] = a.y;
                    v[4*q+2] = a.z; v[4*q+3] = a.w;
                }
            }
        }
        // 4 STS.128: cell kt*4+u holds khalves (kt*8+u, kt*8+u+4)
#pragma unroll
        for (int u = 0; u < 4; u++) {
            uint2 p1 = fpnn_split2(v[2*u],     v[2*u+1]);
            uint2 p2 = fpnn_split2(v[2*u+8],   v[2*u+9]);
            uint4 q; q.x = p1.x; q.y = p1.y; q.z = p2.x; q.w = p2.y;
            A_s[fpnn_swx(nl, kt * 4 + u)] = q;
        }

        // ---- B chunk: fragment-ordered pre-split weights, 4 LDG.128 + 4 STS.128
        {
            const uint4* wsrc = fpnn_wsp4 + ((d * 4 + chunk) * 64 + bn) * 16 + bkg * 4;
#pragma unroll
            for (int u = 0; u < 4; u++)
                B_s[fpnn_swx(bn, bkg * 4 + u)] = wsrc[u];
        }
        __syncthreads();

        // ---- mma: 4 k-steps of 16; fragments via single LDS.128 each ----
#pragma unroll
        for (int ks = 0; ks < 4; ks++) {
            int c = ks * 4 + t;
            uint4 qa0 = A_s[fpnn_swx(m0 + g,     c)];
            uint4 qa1 = A_s[fpnn_swx(m0 + g + 8, c)];
#pragma unroll
            for (int ns = 0; ns < 4; ns++) {
                uint4 qb = B_s[fpnn_swx(n0 + ns * 8 + g, c)];
                FPNN_MMA(acc[ns], qa0.x, qa1.x, qa0.z, qa1.z, qb.x, qb.z); // hi*hi
                FPNN_MMA(acc[ns], qa0.x, qa1.x, qa0.z, qa1.z, qb.y, qb.w); // hi*lo
                FPNN_MMA(acc[ns], qa0.y, qa1.y, qa0.w, qa1.w, qb.x, qb.z); // lo*hi
            }
        }
        __syncthreads();
    }

    // ---- store ----
    int r0 = tile * M_TILE + m0 + g;
    int r1 = r0 + 8;
#pragma unroll
    for (int ns = 0; ns < 4; ns++) {
        int ncol_half = (n0 >> 1) + ns * 4 + t;
        if (r0 < count) {
            int n = list[r0];
            fpnn_pre2[(size_t)n * 32 + ncol_half] = make_float2(acc[ns][0], acc[ns][1]);
        }
        if (r1 < count) {
            int n = list[r1];
            fpnn_pre2[(size_t)n * 32 + ncol_half] = make_float2(acc[ns][2], acc[ns][3]);
        }
    }
}

// ---------------- fused relu + softmax + pool (warp per 8 sorted nodes) ---------
#define NODES_PER_WARP 8
__global__ void fpnn_spool_kernel(const int* __restrict__ b32,
                                  float* __restrict__ out) {
    int warp = (blockIdx.x * blockDim.x + threadIdx.x) >> 5;
    int lane = threadIdx.x & 31;
    int n0 = warp * NODES_PER_WARP;
    if (n0 >= N_NODES) return;
    int st = fpnn_stride;

    float2 acc = make_float2(0.f, 0.f);
    int gcur = b32[(size_t)st * n0];

#pragma unroll
    for (int i = 0; i < NODES_PER_WARP; i++) {
        int n = n0 + i;
        int g = b32[(size_t)st * n];
        if (g != gcur) {
            atomicAdd(out + (size_t)gcur * OUT_CH + 2 * lane,     acc.x);
            atomicAdd(out + (size_t)gcur * OUT_CH + 2 * lane + 1, acc.y);
            acc = make_float2(0.f, 0.f);
            gcur = g;
        }
        float2 v = fpnn_pre2[(size_t)n * 32 + lane];
        v.x = fmaxf(v.x, 0.f);
        v.y = fmaxf(v.y, 0.f);
        float m = fmaxf(v.x, v.y);
#pragma unroll
        for (int s = 16; s; s >>= 1) m = fmaxf(m, __shfl_xor_sync(0xffffffffu, m, s));
        float ex = __expf(v.x - m), ey = __expf(v.y - m);
        float s = ex + ey;
#pragma unroll
        for (int ss = 16; ss; ss >>= 1) s += __shfl_xor_sync(0xffffffffu, s, ss);
        float inv = 1.0f / s;
        acc.x += ex * inv;
        acc.y += ey * inv;
    }
    atomicAdd(out + (size_t)gcur * OUT_CH + 2 * lane,     acc.x);
    atomicAdd(out + (size_t)gcur * OUT_CH + 2 * lane + 1, acc.y);
}

// ---------------- launch ----------------
extern "C" void kernel_launch(void* const* d_in, const int* in_sizes, int n_in,
                              void* d_out, int out_size) {
    const float* x = 0; const int* ei32 = 0; const int* b32 = 0;
    const float* Wlin = 0; const float* Wroot = 0;
    for (int i = 0; i < n_in; i++) {
        int s = in_sizes[i];
        if      (s == N_NODES * IN_CH)        x    = (const float*)d_in[i];
        else if (s == 2 * N_EDGES)            ei32 = (const int*)d_in[i];
        else if (s == N_NODES)                b32  = (const int*)d_in[i];
        else if (s == (MAX_DEG + 1) * IN_CH * OUT_CH) {
            if (!Wlin) Wlin = (const float*)d_in[i];
            else       Wroot = (const float*)d_in[i];
        }
    }
    if (!x)     x     = (const float*)d_in[0];
    if (!ei32)  ei32  = (const int*)d_in[1];
    if (!b32)   b32   = (const int*)d_in[2];
    if (!Wlin)  Wlin  = (const float*)d_in[3];
    if (!Wroot) Wroot = (const float*)d_in[4];
    float* out = (float*)d_out;

    void* p_deg = 0; void* p_cnt = 0;
    cudaGetSymbolAddress(&p_deg, fpnn_deg);
    cudaGetSymbolAddress(&p_cnt, fpnn_cnt);
    cudaMemsetAsync(p_deg, 0, N_NODES * sizeof(int));
    cudaMemsetAsync(p_cnt, 0, 8 * sizeof(int));
    cudaMemsetAsync(d_out, 0, (size_t)out_size * sizeof(float));

    fpnn_deg_kernel<<<(N_EDGES + 255) / 256, 256>>>(ei32);
    fpnn_alloc_kernel<<<(N_NODES + 255) / 256, 256>>>(Wlin, Wroot);
    fpnn_fill_kernel<<<(N_EDGES + 255) / 256, 256>>>(ei32);
    fpnn_mma_kernel<<<MAX_TILES, 256>>>((const float4*)x);
    fpnn_spool_kernel<<<(N_NODES / NODES_PER_WARP * 32 + 255) / 256, 256>>>(b32, out);
}

// round 13
// speedup vs baseline: 1.6115x; 1.0481x over previous
#include <cuda_runtime.h>
#include <cuda_bf16.h>
#include <cstdint>

#define N_NODES  200000
#define N_EDGES  800000
#define IN_CH    128
#define OUT_CH   64
#define MAX_DEG  4
#define N_GRAPHS 8192

// ---------------- scratch ----------------
__device__ int    fpnn_stride;                        // 1 = int32 inputs, 2 = int64
__device__ int    fpnn_deg[N_NODES];
__device__ int    fpnn_off[N_NODES];
__device__ int    fpnn_fill[N_NODES];
__device__ int    fpnn_csr[N_EDGES];
__device__ int    fpnn_cnt[8];                        // [0..4] buckets, [5] cursor
__device__ int    fpnn_lists[(MAX_DEG + 1) * N_NODES];
__device__ uint4  fpnn_wsp4[20480];                   // fragment-ordered split weights
__device__ float2 fpnn_pre2[(size_t)N_NODES * (OUT_CH / 2)];  // 51.2 MB

// ---------------- degree count (+ block-local dtype detect) ----------------
__global__ void fpnn_deg_kernel(const int* __restrict__ ei32) {
    __shared__ int s_st;
    if (threadIdx.x == 0) {
        int nz = 0;
#pragma unroll
        for (int j = 0; j < 8; j++) nz |= ei32[2 * j + 1];
        int st = (nz == 0) ? 2 : 1;
        s_st = st;
        if (blockIdx.x == 0) fpnn_stride = st;
    }
    __syncthreads();
    int e = blockIdx.x * blockDim.x + threadIdx.x;
    if (e >= N_EDGES) return;
    int dst = ei32[(size_t)s_st * (N_EDGES + e)];
    atomicAdd(&fpnn_deg[dst], 1);
}

// ---------------- split-bf16 helpers ----------------
__device__ __forceinline__ unsigned fpnn_pack(float f0, float f1) {
    unsigned u0 = (unsigned)__bfloat16_as_ushort(__float2bfloat16_rn(f0));
    unsigned u1 = (unsigned)__bfloat16_as_ushort(__float2bfloat16_rn(f1));
    return (u1 << 16) | u0;
}
__device__ __forceinline__ uint2 fpnn_split2(float f0, float f1) {
    float h0 = __bfloat162float(__float2bfloat16_rn(f0));
    float h1 = __bfloat162float(__float2bfloat16_rn(f1));
    uint2 p;
    p.x = fpnn_pack(h0, h1);
    p.y = fpnn_pack(f0 - h0, f1 - h1);
    return p;
}
// uint4-cell smem index with XOR bank swizzle; 16 cells per row
__device__ __forceinline__ int fpnn_swx(int row, int c) {
    return row * 16 + (c ^ (row & 7));
}

// ---------------- offset alloc + bucketize + weight pre-split -------------------
// Cell c of a chunk holds the split of chunk float4 position p = (c>>2) + 4*(c&3):
// khalf A = floats (4p, 4p+1), khalf B = floats (4p+2, 4p+3). Matches the A-side
// gather mapping (thread kt, q -> position kt+4q -> cell kt*4+q).
__global__ void fpnn_alloc_kernel(const float* __restrict__ Wlin,
                                  const float* __restrict__ Wroot) {
    int n = blockIdx.x * blockDim.x + threadIdx.x;
    if (n < N_NODES) {
        int deg = fpnn_deg[n];
        fpnn_off[n] = atomicAdd(&fpnn_cnt[5], deg);
        fpnn_fill[n] = 0;
        int d = min(deg, MAX_DEG);
        int pos = atomicAdd(&fpnn_cnt[d], 1);
        fpnn_lists[d * N_NODES + pos] = n;
    }
    if (n < 20480) {
        int cell = n & 15;
        int ch = (n >> 4) & 63;
        int dc = n >> 10;               // d*4 + chunk, 0..19
        int d = dc >> 2, chunk = dc & 3;
        const float* w = (chunk < 2)
            ? Wlin  + (size_t)d * IN_CH * OUT_CH + (size_t)(chunk * 64) * OUT_CH
            : Wroot + (size_t)d * IN_CH * OUT_CH + (size_t)((chunk - 2) * 64) * OUT_CH;
        int p = (cell >> 2) + 4 * (cell & 3);   // float4 position in chunk
        int k0 = p * 4;
        float f0 = w[(size_t)k0 * OUT_CH + ch];
        float f1 = w[(size_t)(k0 + 1) * OUT_CH + ch];
        float f2 = w[(size_t)(k0 + 2) * OUT_CH + ch];
        float f3 = w[(size_t)(k0 + 3) * OUT_CH + ch];
        uint2 p1 = fpnn_split2(f0, f1);
        uint2 p2 = fpnn_split2(f2, f3);
        uint4 q; q.x = p1.x; q.y = p1.y; q.z = p2.x; q.w = p2.y;
        fpnn_wsp4[n] = q;
    }
}

// ---------------- fill CSR ----------------
__global__ void fpnn_fill_kernel(const int* __restrict__ ei32) {
    int e = blockIdx.x * blockDim.x + threadIdx.x;
    if (e >= N_EDGES) return;
    int st = fpnn_stride;
    int src = ei32[(size_t)st * e];
    int dst = ei32[(size_t)st * (N_EDGES + e)];
    int pos = fpnn_off[dst] + atomicAdd(&fpnn_fill[dst], 1);
    fpnn_csr[pos] = src;
}

#define FPNN_MMA(d, a0, a1, a2, a3, b0, b1)                                   \
    asm volatile(                                                             \
        "mma.sync.aligned.m16n8k16.row.col.f32.bf16.bf16.f32 "                \
        "{%0,%1,%2,%3},{%4,%5,%6,%7},{%8,%9},{%0,%1,%2,%3};"                  \
        : "+f"(d[0]), "+f"(d[1]), "+f"(d[2]), "+f"(d[3])                      \
        : "r"(a0), "r"(a1), "r"(a2), "r"(a3), "r"(b0), "r"(b1))

// ---------------- fused gather + split-bf16 tensor GEMM ----------------
// Gather is lane-consecutive: thread (nl, kt) reads float4 positions kt + 4q
// (lanes kt=0..3 cover 64B dense per node per instruction).
#define M_TILE 64
#define MAX_TILES ((N_NODES + M_TILE - 1) / M_TILE + MAX_DEG + 1)   // 3130
__global__ void __launch_bounds__(256, 3)
fpnn_mma_kernel(const float4* __restrict__ x4) {
    __shared__ uint4 A_s[64 * 16];   // [node][cell], 16 KB
    __shared__ uint4 B_s[64 * 16];   // [ch][cell], 16 KB

    int tg = blockIdx.x;
    int d = 0, tile = 0, count = 0;
    {
        int base = 0;
        bool found = false;
#pragma unroll
        for (int b = 0; b <= MAX_DEG; b++) {
            int c = fpnn_cnt[b];
            int t = (c + M_TILE - 1) >> 6;
            if (!found && tg < base + t) {
                d = b; tile = tg - base; count = c; found = true;
            }
            base += t;
        }
        if (!found) return;
    }

    const int* list = fpnn_lists + d * N_NODES;

    int tid = threadIdx.x;
    int nl = tid >> 2, kt = tid & 3;          // A loader: node slot x lane-quarter
    int bn = tid & 63, bkg = tid >> 6;        // B loader: channel x cell-quarter
    int wid = tid >> 5, lane = tid & 31;
    int m0 = (wid & 3) * 16, n0 = (wid >> 2) * 32;
    int g = lane >> 2, t = lane & 3;

    float acc[4][4];
#pragma unroll
    for (int i = 0; i < 4; i++)
#pragma unroll
        for (int j = 0; j < 4; j++) acc[i][j] = 0.f;

#pragma unroll
    for (int chunk = 0; chunk < 4; chunk++) {
        // ---- A chunk: gathered agg (chunks 0,1) or own x (chunks 2,3) ----
        float4 v4[4];
#pragma unroll
        for (int q = 0; q < 4; q++) v4[q] = make_float4(0.f, 0.f, 0.f, 0.f);
        int nidx = tile * M_TILE + nl;
        if (nidx < count) {
            int n = list[nidx];
            if (chunk < 2) {
                int deg = fpnn_deg[n];
                int off = fpnn_off[n];
                for (int i = 0; i < deg; i++) {
                    int src = fpnn_csr[off + i];
                    const float4* r = x4 + (size_t)src * 32 + chunk * 16 + kt;
#pragma unroll
                    for (int q = 0; q < 4; q++) {
                        float4 a = r[4 * q];          // position kt + 4q
                        v4[q].x += a.x; v4[q].y += a.y;
                        v4[q].z += a.z; v4[q].w += a.w;
                    }
                }
            } else {
                const float4* r = x4 + (size_t)n * 32 + (chunk - 2) * 16 + kt;
#pragma unroll
                for (int q = 0; q < 4; q++) v4[q] = r[4 * q];
            }
        }
        // 4 STS.128: cell kt*4+q = split of float4 position kt+4q
#pragma unroll
        for (int q = 0; q < 4; q++) {
            uint2 p1 = fpnn_split2(v4[q].x, v4[q].y);
            uint2 p2 = fpnn_split2(v4[q].z, v4[q].w);
            uint4 qq; qq.x = p1.x; qq.y = p1.y; qq.z = p2.x; qq.w = p2.y;
            A_s[fpnn_swx(nl, kt * 4 + q)] = qq;
        }

        // ---- B chunk: fragment-ordered pre-split weights ----
        {
            const uint4* wsrc = fpnn_wsp4 + ((d * 4 + chunk) * 64 + bn) * 16 + bkg * 4;
#pragma unroll
            for (int u = 0; u < 4; u++)
                B_s[fpnn_swx(bn, bkg * 4 + u)] = wsrc[u];
        }
        __syncthreads();

        // ---- mma: 4 k-steps of 16 ----
#pragma unroll
        for (int ks = 0; ks < 4; ks++) {
            int c = ks * 4 + t;
            uint4 qa0 = A_s[fpnn_swx(m0 + g,     c)];
            uint4 qa1 = A_s[fpnn_swx(m0 + g + 8, c)];
#pragma unroll
            for (int ns = 0; ns < 4; ns++) {
                uint4 qb = B_s[fpnn_swx(n0 + ns * 8 + g, c)];
                FPNN_MMA(acc[ns], qa0.x, qa1.x, qa0.z, qa1.z, qb.x, qb.z); // hi*hi
                FPNN_MMA(acc[ns], qa0.x, qa1.x, qa0.z, qa1.z, qb.y, qb.w); // hi*lo
                FPNN_MMA(acc[ns], qa0.y, qa1.y, qa0.w, qa1.w, qb.x, qb.z); // lo*hi
            }
        }
        __syncthreads();
    }

    // ---- store ----
    int r0 = tile * M_TILE + m0 + g;
    int r1 = r0 + 8;
#pragma unroll
    for (int ns = 0; ns < 4; ns++) {
        int ncol_half = (n0 >> 1) + ns * 4 + t;
        if (r0 < count) {
            int n = list[r0];
            fpnn_pre2[(size_t)n * 32 + ncol_half] = make_float2(acc[ns][0], acc[ns][1]);
        }
        if (r1 < count) {
            int n = list[r1];
            fpnn_pre2[(size_t)n * 32 + ncol_half] = make_float2(acc[ns][2], acc[ns][3]);
        }
    }
}

// ---------------- fused relu + softmax + pool (warp per 8 sorted nodes) ---------
#define NODES_PER_WARP 8
__global__ void fpnn_spool_kernel(const int* __restrict__ b32,
                                  float* __restrict__ out) {
    int warp = (blockIdx.x * blockDim.x + threadIdx.x) >> 5;
    int lane = threadIdx.x & 31;
    int n0 = warp * NODES_PER_WARP;
    if (n0 >= N_NODES) return;
    int st = fpnn_stride;

    float2 acc = make_float2(0.f, 0.f);
    int gcur = b32[(size_t)st * n0];

#pragma unroll
    for (int i = 0; i < NODES_PER_WARP; i++) {
        int n = n0 + i;
        int g = b32[(size_t)st * n];
        if (g != gcur) {
            atomicAdd(out + (size_t)gcur * OUT_CH + 2 * lane,     acc.x);
            atomicAdd(out + (size_t)gcur * OUT_CH + 2 * lane + 1, acc.y);
            acc = make_float2(0.f, 0.f);
            gcur = g;
        }
        float2 v = fpnn_pre2[(size_t)n * 32 + lane];
        v.x = fmaxf(v.x, 0.f);
        v.y = fmaxf(v.y, 0.f);
        float m = fmaxf(v.x, v.y);
#pragma unroll
        for (int s = 16; s; s >>= 1) m = fmaxf(m, __shfl_xor_sync(0xffffffffu, m, s));
        float ex = __expf(v.x - m), ey = __expf(v.y - m);
        float s = ex + ey;
#pragma unroll
        for (int ss = 16; ss; ss >>= 1) s += __shfl_xor_sync(0xffffffffu, s, ss);
        float inv = 1.0f / s;
        acc.x += ex * inv;
        acc.y += ey * inv;
    }
    atomicAdd(out + (size_t)gcur * OUT_CH + 2 * lane,     acc.x);
    atomicAdd(out + (size_t)gcur * OUT_CH + 2 * lane + 1, acc.y);
}

// ---------------- launch ----------------
extern "C" void kernel_launch(void* const* d_in, const int* in_sizes, int n_in,
                              void* d_out, int out_size) {
    const float* x = 0; const int* ei32 = 0; const int* b32 = 0;
    const float* Wlin = 0; const float* Wroot = 0;
    for (int i = 0; i < n_in; i++) {
        int s = in_sizes[i];
        if      (s == N_NODES * IN_CH)        x    = (const float*)d_in[i];
        else if (s == 2 * N_EDGES)            ei32 = (const int*)d_in[i];
        else if (s == N_NODES)                b32  = (const int*)d_in[i];
        else if (s == (MAX_DEG + 1) * IN_CH * OUT_CH) {
            if (!Wlin) Wlin = (const float*)d_in[i];
            else       Wroot = (const float*)d_in[i];
        }
    }
    if (!x)     x     = (const float*)d_in[0];
    if (!ei32)  ei32  = (const int*)d_in[1];
    if (!b32)   b32   = (const int*)d_in[2];
    if (!Wlin)  Wlin  = (const float*)d_in[3];
    if (!Wroot) Wroot = (const float*)d_in[4];
    float* out = (float*)d_out;

    void* p_deg = 0; void* p_cnt = 0;
    cudaGetSymbolAddress(&p_deg, fpnn_deg);
    cudaGetSymbolAddress(&p_cnt, fpnn_cnt);
    cudaMemsetAsync(p_deg, 0, N_NODES * sizeof(int));
    cudaMemsetAsync(p_cnt, 0, 8 * sizeof(int));
    cudaMemsetAsync(d_out, 0, (size_t)out_size * sizeof(float));

    fpnn_deg_kernel<<<(N_EDGES + 255) / 256, 256>>>(ei32);
    fpnn_alloc_kernel<<<(N_NODES + 255) / 256, 256>>>(Wlin, Wroot);
    fpnn_fill_kernel<<<(N_EDGES + 255) / 256, 256>>>(ei32);
    fpnn_mma_kernel<<<MAX_TILES, 256>>>((const float4*)x);
    fpnn_spool_kernel<<<(N_NODES / NODES_PER_WARP * 32 + 255) / 256, 256>>>(b32, out);
}